// round 8
// baseline (speedup 1.0000x reference)
#include <cuda_runtime.h>
#include <math.h>

#define CC   128
#define KK   15
#define HH   32
#define GG   8
#define CPG  16
#define HID  32
#define KG   (KK*GG)      // 120
#define QPB  16
#define MAX_M 30000
#define INV_SIGMA 0.5f
#define NEG_SLOPE 0.1f

// ---- scratch (static device globals: allocation-free) ----
__device__ float  g_pre[MAX_M * CC];
__device__ double g_sum[CC];
__device__ double g_sumsq[CC];
__device__ float  g_scale[CC];
__device__ float  g_shift[CC];

__global__ void init_kernel() {
    int t = threadIdx.x;
    if (t < CC) { g_sum[t] = 0.0; g_sumsq[t] = 0.0; }
}

__global__ __launch_bounds__(128) void main_kernel(
    const float* __restrict__ q_pts,
    const float* __restrict__ s_pts,
    const float* __restrict__ s_feats,
    const int*   __restrict__ nidx,
    const float* __restrict__ kp,
    const float* __restrict__ W1,
    const float* __restrict__ b1,
    const float* __restrict__ W2,
    const float* __restrict__ b2,
    int M)
{
    __shared__ float sm_W1[CC * HID];       // 16 KB, loaded once per block
    __shared__ float sm_kp[KK * 3];
    __shared__ int   sm_idx[HH];
    __shared__ float sm_q[3];
    __shared__ float sm_dx[HH], sm_dy[HH], sm_dz[HH];
    __shared__ float sm_infl[KK * HH];
    __shared__ float sm_center[CC];
    __shared__ float sm_part[4][HID];       // MLP1 partials
    __shared__ float sm_h[HID];
    __shared__ float sm_cw[KG];
    __shared__ float sm_w[HH * GG];         // combined weight w[h][g]

    const int t = threadIdx.x;
    const int c = t;                        // thread == channel
    const int g = c >> 4;

    // one-time block preload (W1 row-major [C][HID]; coalesced, conflict-free reuse)
    #pragma unroll
    for (int i = 0; i < HID; i++)
        sm_W1[i * 128 + t] = __ldg(&W1[i * 128 + t]);
    if (t < KK * 3) sm_kp[t] = __ldg(&kp[t]);

    float lsum = 0.f, lsq = 0.f;
    const int m0 = blockIdx.x * QPB;

    for (int q = 0; q < QPB; q++) {
        const int m = m0 + q;
        if (m >= M) break;                  // uniform across the block

        __syncthreads();                    // protect smem from previous iter / preload

        // phase 1: neighbor indices (warp 0) + query point (warp 1)
        if (t < HH) sm_idx[t] = __ldg(&nidx[m * HH + t]);
        if (t >= HH && t < HH + 3) sm_q[t - HH] = __ldg(&q_pts[m * 3 + (t - HH)]);
        __syncthreads();

        // phase 2: relative positions (warp 0) + center feats (all threads)
        if (t < HH) {
            const int id = sm_idx[t];
            sm_dx[t] = __ldg(&s_pts[id * 3 + 0]) - sm_q[0];
            sm_dy[t] = __ldg(&s_pts[id * 3 + 1]) - sm_q[1];
            sm_dz[t] = __ldg(&s_pts[id * 3 + 2]) - sm_q[2];
        }
        sm_center[c] = __ldg(&s_feats[(size_t)sm_idx[0] * CC + c]);
        __syncthreads();

        // phase 3a: influence[k][h] = max(0, 1 - |d - kp_k|/sigma)  (480 vals)
        for (int i = t; i < KK * HH; i += 128) {
            const int k = i >> 5, h = i & 31;
            const float dx = sm_dx[h] - sm_kp[k * 3 + 0];
            const float dy = sm_dy[h] - sm_kp[k * 3 + 1];
            const float dz = sm_dz[h] - sm_kp[k * 3 + 2];
            const float d  = sqrtf(fmaf(dx, dx, fmaf(dy, dy, dz * dz)));
            sm_infl[i] = fmaxf(1.0f - d * INV_SIGMA, 0.0f);
        }
        // phase 3b: MLP1 partials — all 128 threads: quarter (t>>5) x output (t&31)
        {
            const int part = t >> 5, j = t & 31;
            const int cb = part * 32;
            float a = 0.f;
            #pragma unroll 8
            for (int cc = 0; cc < 32; cc++)
                a = fmaf(sm_center[cb + cc], sm_W1[(cb + cc) * HID + j], a);
            sm_part[part][j] = a;
        }
        __syncthreads();

        // phase 4: reduce MLP1 + leaky relu  (warp 0)
        if (t < HID) {
            float a = __ldg(&b1[t]) + sm_part[0][t] + sm_part[1][t]
                                    + sm_part[2][t] + sm_part[3][t];
            sm_h[t] = (a >= 0.f) ? a : NEG_SLOPE * a;
        }
        __syncthreads();

        // phase 5: MLP2 -> conv_w[k*G+g]  (120 threads; W2 L1/L2-resident)
        if (t < KG) {
            float a = __ldg(&b2[t]);
            #pragma unroll
            for (int j = 0; j < HID; j++)
                a = fmaf(sm_h[j], __ldg(&W2[j * KG + t]), a);
            sm_cw[t] = a;
        }
        __syncthreads();

        // phase 6: combined weight w[h][g] = sum_k cw[k*G+g] * infl[k*HH+h]
        for (int i = t; i < HH * GG; i += 128) {
            const int h = i >> 3, gg = i & 7;
            float a = 0.f;
            #pragma unroll
            for (int k = 0; k < KK; k++)
                a = fmaf(sm_cw[k * GG + gg], sm_infl[k * HH + h], a);
            sm_w[i] = a;
        }
        __syncthreads();

        // phase 7: out[c] = sum_h w[h][g] * feats[idx[h]][c]   (hot loop, L2-bound)
        float o = 0.f;
        #pragma unroll 8
        for (int h = 0; h < HH; h++) {
            const float f = __ldg(&s_feats[(size_t)sm_idx[h] * CC + c]);
            o = fmaf(sm_w[h * GG + g], f, o);
        }

        __stcs(&g_pre[(size_t)m * CC + c], o);   // streaming store: don't pollute L1
        lsum += o;
        lsq = fmaf(o, o, lsq);
    }

    // block-local stats -> global (1875 atomics per channel address)
    atomicAdd(&g_sum[c],   (double)lsum);
    atomicAdd(&g_sumsq[c], (double)lsq);
}

__global__ void stats_kernel(const float* __restrict__ gamma,
                             const float* __restrict__ beta, int M) {
    const int cidx = threadIdx.x;
    if (cidx < CC) {
        const double invM = 1.0 / (double)M;
        const double mean = g_sum[cidx] * invM;
        const double var  = g_sumsq[cidx] * invM - mean * mean;
        const float rstd  = (float)(1.0 / sqrt(var + 1e-5));
        const float sc    = rstd * __ldg(&gamma[cidx]);
        g_scale[cidx] = sc;
        g_shift[cidx] = __ldg(&beta[cidx]) - (float)mean * sc;
    }
}

__global__ __launch_bounds__(256) void norm_kernel(float* __restrict__ out, int total4) {
    const int i = blockIdx.x * blockDim.x + threadIdx.x;
    if (i >= total4) return;
    const float4 v = __ldcs(&reinterpret_cast<const float4*>(g_pre)[i]);  // evict-first
    const int c0 = (i * 4) & (CC - 1);
    float4 r;
    float x;
    x = fmaf(v.x, g_scale[c0 + 0], g_shift[c0 + 0]); r.x = (x >= 0.f) ? x : NEG_SLOPE * x;
    x = fmaf(v.y, g_scale[c0 + 1], g_shift[c0 + 1]); r.y = (x >= 0.f) ? x : NEG_SLOPE * x;
    x = fmaf(v.z, g_scale[c0 + 2], g_shift[c0 + 2]); r.z = (x >= 0.f) ? x : NEG_SLOPE * x;
    x = fmaf(v.w, g_scale[c0 + 3], g_shift[c0 + 3]); r.w = (x >= 0.f) ? x : NEG_SLOPE * x;
    reinterpret_cast<float4*>(out)[i] = r;
}

extern "C" void kernel_launch(void* const* d_in, const int* in_sizes, int n_in,
                              void* d_out, int out_size) {
    const float* q_pts   = (const float*)d_in[0];
    const float* s_pts   = (const float*)d_in[1];
    const float* s_feats = (const float*)d_in[2];
    const int*   nidx    = (const int*)  d_in[3];
    const float* kp      = (const float*)d_in[4];
    const float* W1      = (const float*)d_in[5];
    const float* b1      = (const float*)d_in[6];
    const float* W2      = (const float*)d_in[7];
    const float* b2      = (const float*)d_in[8];
    const float* gamma   = (const float*)d_in[9];
    const float* beta    = (const float*)d_in[10];
    float* out = (float*)d_out;

    const int M = in_sizes[0] / 3;

    init_kernel<<<1, 128>>>();
    main_kernel<<<(M + QPB - 1) / QPB, 128>>>(q_pts, s_pts, s_feats, nidx, kp,
                                              W1, b1, W2, b2, M);
    stats_kernel<<<1, 128>>>(gamma, beta, M);
    const int total4 = M * CC / 4;
    norm_kernel<<<(total4 + 255) / 256, 256>>>(out, total4);
}

// round 14
// speedup vs baseline: 1.4580x; 1.4580x over previous
#include <cuda_runtime.h>
#include <math.h>

#define CC   128
#define KK   15
#define HH   32
#define GG   8
#define HID  32
#define KG   120
#define NEG_SLOPE 0.1f
#define MAX_M 30000
#define WARPS 8
#define QPW   4
#define NTHREADS 256
#define FULLMASK 0xffffffffu

// ---- scratch (static device globals: allocation-free) ----
__device__ __align__(16) float g_pre[MAX_M * CC];
__device__ double g_sum[CC];
__device__ double g_sumsq[CC];
__device__ float  g_scale[CC];
__device__ float  g_shift[CC];

__global__ void init_kernel() {
    int t = threadIdx.x;
    if (t < CC) { g_sum[t] = 0.0; g_sumsq[t] = 0.0; }
}

// One warp per query; lane owns channels 4*lane..4*lane+3 (single group g = lane>>2).
__global__ __launch_bounds__(NTHREADS) void main_kernel(
    const float* __restrict__ q_pts,
    const float* __restrict__ s_pts,
    const float* __restrict__ s_feats,
    const int*   __restrict__ nidx,
    const float* __restrict__ kp,
    const float* __restrict__ W1,
    const float* __restrict__ b1,
    const float* __restrict__ W2,
    const float* __restrict__ b2,
    int M)
{
    __shared__ __align__(16) float sW1[CC * HID];       // 16 KB  [c][j]
    __shared__ __align__(16) float sW2[HID * KG + 8];   // 15.4 KB [j][i], +pad for lane30/31 overread
    __shared__ __align__(16) float sCtrCW[WARPS][CC];   // union: center feats / conv_w (float4 access)
    __shared__ __align__(16) float sWw[WARPS][HH * GG]; // combined weight w[h][g]
    __shared__ __align__(16) float sB2[128];            // padded 120->128
    __shared__ float sKP[KK * 3];
    __shared__ float sB1[HID];
    __shared__ float sH[WARPS][HID];
    __shared__ float sStat[2][CC];

    const int t = threadIdx.x, warp = t >> 5, lane = t & 31;

    for (int i = t; i < CC * HID; i += NTHREADS) sW1[i] = __ldg(&W1[i]);
    for (int i = t; i < HID * KG; i += NTHREADS) sW2[i] = __ldg(&W2[i]);
    if (t < KK * 3) sKP[t] = __ldg(&kp[t]);
    if (t < HID)    sB1[t] = __ldg(&b1[t]);
    if (t < 128)    sB2[t] = (t < KG) ? __ldg(&b2[t]) : 0.f;
    if (t < CC) { sStat[0][t] = 0.f; sStat[1][t] = 0.f; }
    __syncthreads();

    const float4* f4 = (const float4*)s_feats;
    const int gsel = lane >> 2;
    float s0=0.f,s1=0.f,s2=0.f,s3=0.f, e0=0.f,e1=0.f,e2=0.f,e3=0.f;
    const int gw = blockIdx.x * WARPS + warp;

    for (int qi = 0; qi < QPW; qi++) {
        const int m = gw * QPW + qi;
        if (m < M) {                          // uniform across the warp
            // neighbor index (lane = neighbor h) + query point + rel pos
            const int idx = __ldg(&nidx[m * HH + lane]);
            const float qx = __ldg(&q_pts[3*m]), qy = __ldg(&q_pts[3*m+1]), qz = __ldg(&q_pts[3*m+2]);
            const float dx = __ldg(&s_pts[3*idx])   - qx;
            const float dy = __ldg(&s_pts[3*idx+1]) - qy;
            const float dz = __ldg(&s_pts[3*idx+2]) - qz;

            // influence[k] for this lane's neighbor (registers)
            float infl[KK];
            #pragma unroll
            for (int k = 0; k < KK; k++) {
                const float ax = dx - sKP[3*k], ay = dy - sKP[3*k+1], az = dz - sKP[3*k+2];
                const float d  = sqrtf(fmaf(ax, ax, fmaf(ay, ay, az * az)));
                infl[k] = fmaxf(1.f - 0.5f * d, 0.f);
            }

            // center feats (neighbor 0) -> smem stage
            const int idx0 = __shfl_sync(FULLMASK, idx, 0);
            const float4 ctr = __ldg(&f4[(size_t)idx0 * 32 + lane]);
            ((float4*)sCtrCW[warp])[lane] = ctr;
            __syncwarp();                                        // (A)

            // MLP1: h1[lane] = leaky(b1 + sum_c center[c]*W1[c][lane])
            float h1 = sB1[lane];
            #pragma unroll 16
            for (int c = 0; c < CC; c++)
                h1 = fmaf(sCtrCW[warp][c], sW1[c * HID + lane], h1);
            h1 = (h1 >= 0.f) ? h1 : NEG_SLOPE * h1;
            sH[warp][lane] = h1;
            __syncwarp();                                        // (B)

            // MLP2: lane computes outputs 4*lane..4*lane+3 (lanes 30/31 garbage, unused)
            float4 cw;
            cw.x = sB2[4*lane]; cw.y = sB2[4*lane+1]; cw.z = sB2[4*lane+2]; cw.w = sB2[4*lane+3];
            #pragma unroll
            for (int j = 0; j < HID; j++) {
                const float hj = sH[warp][j];
                const float4 w2 = *(const float4*)(sW2 + j * KG + 4*lane);
                cw.x = fmaf(hj, w2.x, cw.x); cw.y = fmaf(hj, w2.y, cw.y);
                cw.z = fmaf(hj, w2.z, cw.z); cw.w = fmaf(hj, w2.w, cw.w);
            }
            ((float4*)sCtrCW[warp])[lane] = cw;   // reuse union as conv_w[0..119]
            __syncwarp();                                        // (C)

            // combined weight: w[h=lane][g] = sum_k infl[k] * cw[k*8+g]
            #pragma unroll
            for (int g = 0; g < GG; g++) {
                float a = 0.f;
                #pragma unroll
                for (int k = 0; k < KK; k++)
                    a = fmaf(infl[k], sCtrCW[warp][k * GG + g], a);
                sWw[warp][lane * GG + g] = a;
            }
            __syncwarp();                                        // (D)

            // hot gather: one full 512B s_feats row per warp-instruction
            float4 o; o.x = o.y = o.z = o.w = 0.f;
            #pragma unroll 8
            for (int h = 0; h < HH; h++) {
                const int ih = __shfl_sync(FULLMASK, idx, h);
                const float4 f = __ldg(&f4[(size_t)ih * 32 + lane]);
                const float wv = sWw[warp][h * GG + gsel];
                o.x = fmaf(wv, f.x, o.x); o.y = fmaf(wv, f.y, o.y);
                o.z = fmaf(wv, f.z, o.z); o.w = fmaf(wv, f.w, o.w);
            }

            __stcs(&((float4*)g_pre)[(size_t)m * 32 + lane], o);
            s0 += o.x; s1 += o.y; s2 += o.z; s3 += o.w;
            e0 = fmaf(o.x,o.x,e0); e1 = fmaf(o.y,o.y,e1);
            e2 = fmaf(o.z,o.z,e2); e3 = fmaf(o.w,o.w,e3);
        }
    }

    // block-level stat reduction (smem float), then 1 double atomic per channel per block
    atomicAdd(&sStat[0][4*lane+0], s0); atomicAdd(&sStat[0][4*lane+1], s1);
    atomicAdd(&sStat[0][4*lane+2], s2); atomicAdd(&sStat[0][4*lane+3], s3);
    atomicAdd(&sStat[1][4*lane+0], e0); atomicAdd(&sStat[1][4*lane+1], e1);
    atomicAdd(&sStat[1][4*lane+2], e2); atomicAdd(&sStat[1][4*lane+3], e3);
    __syncthreads();
    if (t < CC) atomicAdd(&g_sum[t],        (double)sStat[0][t]);
    else        atomicAdd(&g_sumsq[t - CC], (double)sStat[1][t - CC]);
}

__global__ void stats_kernel(const float* __restrict__ gamma,
                             const float* __restrict__ beta, int M) {
    const int cidx = threadIdx.x;
    if (cidx < CC) {
        const double invM = 1.0 / (double)M;
        const double mean = g_sum[cidx] * invM;
        const double var  = g_sumsq[cidx] * invM - mean * mean;
        const float rstd  = (float)(1.0 / sqrt(var + 1e-5));
        const float sc    = rstd * __ldg(&gamma[cidx]);
        g_scale[cidx] = sc;
        g_shift[cidx] = __ldg(&beta[cidx]) - (float)mean * sc;
    }
}

__global__ __launch_bounds__(256) void norm_kernel(float* __restrict__ out, int total4) {
    const int i = blockIdx.x * blockDim.x + threadIdx.x;
    if (i >= total4) return;
    const float4 v = __ldcs(&reinterpret_cast<const float4*>(g_pre)[i]);
    const int c0 = (i * 4) & (CC - 1);
    float4 r;
    float x;
    x = fmaf(v.x, g_scale[c0 + 0], g_shift[c0 + 0]); r.x = (x >= 0.f) ? x : NEG_SLOPE * x;
    x = fmaf(v.y, g_scale[c0 + 1], g_shift[c0 + 1]); r.y = (x >= 0.f) ? x : NEG_SLOPE * x;
    x = fmaf(v.z, g_scale[c0 + 2], g_shift[c0 + 2]); r.z = (x >= 0.f) ? x : NEG_SLOPE * x;
    x = fmaf(v.w, g_scale[c0 + 3], g_shift[c0 + 3]); r.w = (x >= 0.f) ? x : NEG_SLOPE * x;
    reinterpret_cast<float4*>(out)[i] = r;
}

extern "C" void kernel_launch(void* const* d_in, const int* in_sizes, int n_in,
                              void* d_out, int out_size) {
    const float* q_pts   = (const float*)d_in[0];
    const float* s_pts   = (const float*)d_in[1];
    const float* s_feats = (const float*)d_in[2];
    const int*   nidx    = (const int*)  d_in[3];
    const float* kp      = (const float*)d_in[4];
    const float* W1      = (const float*)d_in[5];
    const float* b1      = (const float*)d_in[6];
    const float* W2      = (const float*)d_in[7];
    const float* b2      = (const float*)d_in[8];
    const float* gamma   = (const float*)d_in[9];
    const float* beta    = (const float*)d_in[10];
    float* out = (float*)d_out;

    const int M = in_sizes[0] / 3;
    const int qpb = WARPS * QPW;

    init_kernel<<<1, 128>>>();
    main_kernel<<<(M + qpb - 1) / qpb, NTHREADS>>>(q_pts, s_pts, s_feats, nidx, kp,
                                                   W1, b1, W2, b2, M);
    stats_kernel<<<1, 128>>>(gamma, beta, M);
    const int total4 = M * CC / 4;
    norm_kernel<<<(total4 + 255) / 256, 256>>>(out, total4);
}

// round 17
// speedup vs baseline: 1.5168x; 1.0403x over previous
#include <cuda_runtime.h>
#include <cuda_fp16.h>
#include <math.h>

#define CC   128
#define KK   15
#define HH   32
#define GG   8
#define HID  32
#define KG   120
#define NEG_SLOPE 0.1f
#define MAX_M 30000
#define MAX_N 30000
#define WARPS 8
#define QPW   4
#define NTHREADS 256
#define FULLMASK 0xffffffffu

// ---- scratch (static device globals: allocation-free) ----
__device__ __align__(16) float  g_pre[MAX_M * CC];
__device__ __align__(16) __half g_fh[MAX_N * CC];   // fp16-staged s_feats
__device__ double g_sum[CC];
__device__ double g_sumsq[CC];
__device__ float  g_scale[CC];
__device__ float  g_shift[CC];

// stage s_feats fp32 -> fp16 (read float4, write half4 as uint2)
__global__ __launch_bounds__(256) void convert_kernel(const float* __restrict__ sf, int total4) {
    const int i = blockIdx.x * blockDim.x + threadIdx.x;
    if (i >= total4) return;
    const float4 v = __ldg(&((const float4*)sf)[i]);
    const __half2 a = __floats2half2_rn(v.x, v.y);
    const __half2 b = __floats2half2_rn(v.z, v.w);
    uint2 o;
    o.x = *(const unsigned int*)&a;
    o.y = *(const unsigned int*)&b;
    ((uint2*)g_fh)[i] = o;
}

// One warp per query; lane owns channels 4*lane..4*lane+3 (group g = lane>>2).
__global__ __launch_bounds__(NTHREADS) void main_kernel(
    const float* __restrict__ q_pts,
    const float* __restrict__ s_pts,
    const float* __restrict__ s_feats,
    const int*   __restrict__ nidx,
    const float* __restrict__ kp,
    const float* __restrict__ W1,
    const float* __restrict__ b1,
    const float* __restrict__ W2,
    const float* __restrict__ b2,
    int M)
{
    __shared__ __align__(16) float sW1[CC * HID];       // 16 KB  [c][j]
    __shared__ __align__(16) float sW2[HID * KG + 8];   // 15.4 KB [j][i], +pad for lane30/31 overread
    __shared__ __align__(16) float sCtrCW[WARPS][CC];   // union: center feats / conv_w
    __shared__ __align__(16) float sWw[WARPS][HH * GG]; // combined weight w[h][g]
    __shared__ __align__(16) float sB2[128];            // padded 120->128
    __shared__ float sKP[KK * 3];
    __shared__ float sB1[HID];
    __shared__ float sH[WARPS][HID];
    __shared__ float sStat[2][CC];

    const int t = threadIdx.x, warp = t >> 5, lane = t & 31;

    for (int i = t; i < CC * HID; i += NTHREADS) sW1[i] = __ldg(&W1[i]);
    for (int i = t; i < HID * KG; i += NTHREADS) sW2[i] = __ldg(&W2[i]);
    if (t < KK * 3) sKP[t] = __ldg(&kp[t]);
    if (t < HID)    sB1[t] = __ldg(&b1[t]);
    if (t < 128)    sB2[t] = (t < KG) ? __ldg(&b2[t]) : 0.f;
    if (t < CC) { sStat[0][t] = 0.f; sStat[1][t] = 0.f; }
    __syncthreads();

    const float4* f4  = (const float4*)s_feats;       // fp32 (center feats only)
    const uint2*  fh  = (const uint2*)g_fh;           // fp16 table (hot gather)
    const int gsel = lane >> 2;
    float s0=0.f,s1=0.f,s2=0.f,s3=0.f, e0=0.f,e1=0.f,e2=0.f,e3=0.f;
    const int gw = blockIdx.x * WARPS + warp;

    for (int qi = 0; qi < QPW; qi++) {
        const int m = gw * QPW + qi;
        if (m < M) {                          // uniform across the warp
            const int idx = __ldg(&nidx[m * HH + lane]);
            const float qx = __ldg(&q_pts[3*m]), qy = __ldg(&q_pts[3*m+1]), qz = __ldg(&q_pts[3*m+2]);
            const float dx = __ldg(&s_pts[3*idx])   - qx;
            const float dy = __ldg(&s_pts[3*idx+1]) - qy;
            const float dz = __ldg(&s_pts[3*idx+2]) - qz;

            // influence[k] for this lane's neighbor
            float infl[KK];
            #pragma unroll
            for (int k = 0; k < KK; k++) {
                const float ax = dx - sKP[3*k], ay = dy - sKP[3*k+1], az = dz - sKP[3*k+2];
                const float d  = sqrtf(fmaf(ax, ax, fmaf(ay, ay, az * az)));
                infl[k] = fmaxf(1.f - 0.5f * d, 0.f);
            }

            // center feats (neighbor 0, fp32) -> smem stage
            const int idx0 = __shfl_sync(FULLMASK, idx, 0);
            const float4 ctr = __ldg(&f4[(size_t)idx0 * 32 + lane]);
            ((float4*)sCtrCW[warp])[lane] = ctr;
            __syncwarp();                                        // (A)

            // MLP1 (4 independent chains): h1[lane]
            float a0=0.f,a1=0.f,a2=0.f,a3=0.f;
            #pragma unroll 8
            for (int c = 0; c < CC; c += 4) {
                a0 = fmaf(sCtrCW[warp][c+0], sW1[(c+0) * HID + lane], a0);
                a1 = fmaf(sCtrCW[warp][c+1], sW1[(c+1) * HID + lane], a1);
                a2 = fmaf(sCtrCW[warp][c+2], sW1[(c+2) * HID + lane], a2);
                a3 = fmaf(sCtrCW[warp][c+3], sW1[(c+3) * HID + lane], a3);
            }
            float h1 = sB1[lane] + ((a0 + a1) + (a2 + a3));
            h1 = (h1 >= 0.f) ? h1 : NEG_SLOPE * h1;
            sH[warp][lane] = h1;
            __syncwarp();                                        // (B)

            // MLP2: lane computes outputs 4*lane..4*lane+3 (lanes 30/31 garbage, unused)
            float4 cw;
            cw.x = sB2[4*lane]; cw.y = sB2[4*lane+1]; cw.z = sB2[4*lane+2]; cw.w = sB2[4*lane+3];
            #pragma unroll
            for (int j = 0; j < HID; j++) {
                const float hj = sH[warp][j];
                const float4 w2 = *(const float4*)(sW2 + j * KG + 4*lane);
                cw.x = fmaf(hj, w2.x, cw.x); cw.y = fmaf(hj, w2.y, cw.y);
                cw.z = fmaf(hj, w2.z, cw.z); cw.w = fmaf(hj, w2.w, cw.w);
            }
            ((float4*)sCtrCW[warp])[lane] = cw;   // reuse union as conv_w[0..119]
            __syncwarp();                                        // (C)

            // combined weight: w[h=lane][g] = sum_k infl[k] * cw[k*8+g]
            #pragma unroll
            for (int g = 0; g < GG; g++) {
                float a = 0.f;
                #pragma unroll
                for (int k = 0; k < KK; k++)
                    a = fmaf(infl[k], sCtrCW[warp][k * GG + g], a);
                sWw[warp][lane * GG + g] = a;
            }
            __syncwarp();                                        // (D)

            // hot gather (fp16 rows: 256B per warp-instruction, half the L2 bytes)
            float4 o; o.x = o.y = o.z = o.w = 0.f;
            #pragma unroll 8
            for (int h = 0; h < HH; h++) {
                const int ih = __shfl_sync(FULLMASK, idx, h);
                const uint2 hv = __ldg(&fh[(size_t)ih * 32 + lane]);
                const float2 f01 = __half22float2(*(const __half2*)&hv.x);
                const float2 f23 = __half22float2(*(const __half2*)&hv.y);
                const float wv = sWw[warp][h * GG + gsel];
                o.x = fmaf(wv, f01.x, o.x); o.y = fmaf(wv, f01.y, o.y);
                o.z = fmaf(wv, f23.x, o.z); o.w = fmaf(wv, f23.y, o.w);
            }

            __stcs(&((float4*)g_pre)[(size_t)m * 32 + lane], o);
            s0 += o.x; s1 += o.y; s2 += o.z; s3 += o.w;
            e0 = fmaf(o.x,o.x,e0); e1 = fmaf(o.y,o.y,e1);
            e2 = fmaf(o.z,o.z,e2); e3 = fmaf(o.w,o.w,e3);
        }
    }

    // block-level stat reduction (smem float), then 1 double atomic per channel per block
    atomicAdd(&sStat[0][4*lane+0], s0); atomicAdd(&sStat[0][4*lane+1], s1);
    atomicAdd(&sStat[0][4*lane+2], s2); atomicAdd(&sStat[0][4*lane+3], s3);
    atomicAdd(&sStat[1][4*lane+0], e0); atomicAdd(&sStat[1][4*lane+1], e1);
    atomicAdd(&sStat[1][4*lane+2], e2); atomicAdd(&sStat[1][4*lane+3], e3);
    __syncthreads();
    if (t < CC) atomicAdd(&g_sum[t],        (double)sStat[0][t]);
    else        atomicAdd(&g_sumsq[t - CC], (double)sStat[1][t - CC]);
}

// computes scale/shift AND resets accumulators (keeps globals zeroed for next replay)
__global__ void stats_kernel(const float* __restrict__ gamma,
                             const float* __restrict__ beta, int M) {
    const int cidx = threadIdx.x;
    if (cidx < CC) {
        const double invM = 1.0 / (double)M;
        const double mean = g_sum[cidx] * invM;
        const double var  = g_sumsq[cidx] * invM - mean * mean;
        const float rstd  = (float)(1.0 / sqrt(var + 1e-5));
        const float sc    = rstd * __ldg(&gamma[cidx]);
        g_scale[cidx] = sc;
        g_shift[cidx] = __ldg(&beta[cidx]) - (float)mean * sc;
        g_sum[cidx] = 0.0; g_sumsq[cidx] = 0.0;   // reset for next graph replay
    }
}

__global__ __launch_bounds__(256) void norm_kernel(float* __restrict__ out, int total4) {
    const int i = blockIdx.x * blockDim.x + threadIdx.x;
    if (i >= total4) return;
    const float4 v = __ldcs(&reinterpret_cast<const float4*>(g_pre)[i]);
    const int c0 = (i * 4) & (CC - 1);
    float4 r;
    float x;
    x = fmaf(v.x, g_scale[c0 + 0], g_shift[c0 + 0]); r.x = (x >= 0.f) ? x : NEG_SLOPE * x;
    x = fmaf(v.y, g_scale[c0 + 1], g_shift[c0 + 1]); r.y = (x >= 0.f) ? x : NEG_SLOPE * x;
    x = fmaf(v.z, g_scale[c0 + 2], g_shift[c0 + 2]); r.z = (x >= 0.f) ? x : NEG_SLOPE * x;
    x = fmaf(v.w, g_scale[c0 + 3], g_shift[c0 + 3]); r.w = (x >= 0.f) ? x : NEG_SLOPE * x;
    reinterpret_cast<float4*>(out)[i] = r;
}

extern "C" void kernel_launch(void* const* d_in, const int* in_sizes, int n_in,
                              void* d_out, int out_size) {
    const float* q_pts   = (const float*)d_in[0];
    const float* s_pts   = (const float*)d_in[1];
    const float* s_feats = (const float*)d_in[2];
    const int*   nidx    = (const int*)  d_in[3];
    const float* kp      = (const float*)d_in[4];
    const float* W1      = (const float*)d_in[5];
    const float* b1      = (const float*)d_in[6];
    const float* W2      = (const float*)d_in[7];
    const float* b2      = (const float*)d_in[8];
    const float* gamma   = (const float*)d_in[9];
    const float* beta    = (const float*)d_in[10];
    float* out = (float*)d_out;

    const int M = in_sizes[0] / 3;
    const int feat4 = in_sizes[2] / 4;            // N*C/4 float4s
    const int qpb = WARPS * QPW;

    convert_kernel<<<(feat4 + 255) / 256, 256>>>(s_feats, feat4);
    main_kernel<<<(M + qpb - 1) / qpb, NTHREADS>>>(q_pts, s_pts, s_feats, nidx, kp,
                                                   W1, b1, W2, b2, M);
    stats_kernel<<<1, 128>>>(gamma, beta, M);
    const int total4 = M * CC / 4;
    norm_kernel<<<(total4 + 255) / 256, 256>>>(out, total4);
}